// round 17
// baseline (speedup 1.0000x reference)
#include <cuda_runtime.h>
#include <cuda_fp16.h>
#include <cstdint>

// ---------------------------------------------------------------------------
// NCA step, persistent-CTA tensor-core version (mma.sync fp16, f32 accum).
// Warp grid 4m x 4n (warp = m32 x n24): B1 AND B2 fragments live in
// REGISTERS for the whole kernel (tile-invariant) -> stage-1 ldsm is A-only.
// Patch loaded via cp.async (no register prefetch). Stage-2 4-way K-split
// with k8-half zero-padding at quarter boundaries; partials f32-summed in
// SMEM. Single-fp16 operands (rel err ~1.4e-4 < 1e-3).
//   stage1: h = im2col(x)[128px x 109] @ W1comb[109 x 96]  (bias as K-col)
//   stage2: upd = relu(h) @ W2t[96 x 12] + b2
//   out = x + upd * (mask > 0.5)
// ---------------------------------------------------------------------------

#define Bn   16
#define Cn   12
#define Hn   384
#define Wn   384
#define CHn  96
#define PIX  128
#define NT   (3 * Hn * Bn)     // 18432 tiles
#define NCTA 148
#define NTHR 512
#define PATCHN (Cn * 3 * 130)  // 4680

#define ASTR 240               // A row stride bytes (112 k-slots + pad)
#define BSTR 48                // Bt row stride bytes (16 k-slots + pad)
#define USTR 17                // upd row stride (words); gcd(17,32)=1

// SMEM layout (bytes)
#define SM_A     0             // A fp16: 128 x 240 = 30720
#define SM_B1    30720         // B1t fp16: 672 x 48 = 32256
#define SM_B2    62976         // B2t fp16: 96 x 48 = 4608
#define SM_UPD   67584         // partials: 4 x 128 x 17 f32 = 34816
#define SM_PATCH 102400        // fp32 patch: 4680 floats = 18720
#define SM_TOTAL 121120

// Weight images (written by fold kernel)
__device__ unsigned char g_B1img[32256];
__device__ unsigned char g_B2img[4608];

static __device__ __forceinline__ uint32_t smem_u32(const void* p) {
    uint32_t a;
    asm("{ .reg .u64 t; cvta.to.shared.u64 t, %1; cvt.u32.u64 %0, t; }"
        : "=r"(a) : "l"(p));
    return a;
}
static __device__ __forceinline__ void ldsm4(uint32_t* r, uint32_t addr) {
    asm volatile("ldmatrix.sync.aligned.m8n8.x4.shared.b16 {%0,%1,%2,%3}, [%4];"
        : "=r"(r[0]), "=r"(r[1]), "=r"(r[2]), "=r"(r[3]) : "r"(addr));
}
static __device__ __forceinline__ void ldsm2(uint32_t* r, uint32_t addr) {
    asm volatile("ldmatrix.sync.aligned.m8n8.x2.shared.b16 {%0,%1}, [%2];"
        : "=r"(r[0]), "=r"(r[1]) : "r"(addr));
}
static __device__ __forceinline__ void mma16816(float* d, const uint32_t* a,
                                                uint32_t b0, uint32_t b1) {
    asm volatile(
        "mma.sync.aligned.m16n8k16.row.col.f32.f16.f16.f32 "
        "{%0,%1,%2,%3}, {%4,%5,%6,%7}, {%8,%9}, {%0,%1,%2,%3};"
        : "+f"(d[0]), "+f"(d[1]), "+f"(d[2]), "+f"(d[3])
        : "r"(a[0]), "r"(a[1]), "r"(a[2]), "r"(a[3]), "r"(b0), "r"(b1));
}
static __device__ __forceinline__ uint32_t packh(float v0, float v1) {
    __half2 h = __floats2half2_rn(v0, v1);     // .x = v0 (low half)
    return *reinterpret_cast<uint32_t*>(&h);
}
static __device__ __forceinline__ uint32_t packrelu(float v0, float v1) {
    return packh(fmaxf(v0, 0.f), fmaxf(v1, 0.f));
}
static __device__ __forceinline__ void cp4(uint32_t smem_addr,
                                           const float* g) {
    asm volatile("cp.async.ca.shared.global [%0], [%1], 4;"
                 :: "r"(smem_addr), "l"(g) : "memory");
}
#define CP_COMMIT() asm volatile("cp.async.commit_group;" ::: "memory")
#define CP_WAIT0()  asm volatile("cp.async.wait_group 0;" ::: "memory")

static __device__ __forceinline__ float a_val(const float* pf, int px, int k) {
    if (k >= 108) return (k == 108) ? 1.f : 0.f;
    int c = k / 9, rem = k - c * 9;
    int dy = rem / 3, dx = rem - dy * 3;
    return pf[(c * 3 + dy) * 130 + px + dx];
}

// A build (fp16) for k-range [KBASE, KBASE+NSLOT); aligned STS.128,
// conflict-free at 240B lane stride.
template <int KBASE, int NSLOT>
static __device__ __forceinline__ void buildA(const float* pf, int px,
                                              char* Ah) {
#pragma unroll
    for (int g = 0; g < NSLOT / 8; ++g) {
        const int k0 = KBASE + g * 8;
        uint4 hv;
        hv.x = packh(a_val(pf, px, k0 + 0), a_val(pf, px, k0 + 1));
        hv.y = packh(a_val(pf, px, k0 + 2), a_val(pf, px, k0 + 3));
        hv.z = packh(a_val(pf, px, k0 + 4), a_val(pf, px, k0 + 5));
        hv.w = packh(a_val(pf, px, k0 + 6), a_val(pf, px, k0 + 7));
        *(uint4*)(Ah + k0 * 2) = hv;
    }
}

// ---------------------------------------------------------------------------
// Fold: W1comb[k][o] = sum_p w1[o][p]*wperc[p][k]; Bt[n][k] row layout:
// B1 row = (k>>4)*96 + o (k=108 -> b1; 109..111 zero), B2 row =
// (j>>4)*16 + oc; 48B stride; single fp16.
// ---------------------------------------------------------------------------
__global__ void fold_kernel(const float* __restrict__ w1,
                            const float* __restrict__ wperc,
                            const float* __restrict__ b1,
                            const float* __restrict__ w2) {
    int tid = threadIdx.x;   // 512 threads, 1 block
    for (int i = tid; i < 32256 / 4; i += NTHR) ((uint32_t*)g_B1img)[i] = 0;
    for (int i = tid; i < 4608 / 4;  i += NTHR) ((uint32_t*)g_B2img)[i] = 0;
    __syncthreads();
    for (int idx = tid; idx < 109 * CHn; idx += NTHR) {
        int k = idx / CHn, o = idx % CHn;
        float v;
        if (k < 108) {
            v = 0.f;
            for (int p = 0; p < 48; ++p)
                v = fmaf(w1[o * 48 + p], wperc[p * 108 + k], v);
        } else v = b1[o];
        __half h = __float2half_rn(v);
        int off = ((k >> 4) * 96 + o) * BSTR + (k & 15) * 2;
        *(uint16_t*)(g_B1img + off) = *(uint16_t*)&h;
    }
    for (int idx = tid; idx < 96 * Cn; idx += NTHR) {
        int j = idx / Cn, oc = idx % Cn;
        __half h = __float2half_rn(w2[oc * CHn + j]);
        int off = ((j >> 4) * 16 + oc) * BSTR + (j & 15) * 2;
        *(uint16_t*)(g_B2img + off) = *(uint16_t*)&h;
    }
}

// issue cp.async loads of a tile's patch into SMEM (wrap applied)
static __device__ __forceinline__ void prefetch_cp(
    const float* __restrict__ x, int tile, int tid, uint32_t patch_smem) {
    int seg = tile % 3, t1 = tile / 3;
    int gy = t1 % Hn, b = t1 / Hn, x0 = seg * PIX;
    int ym1 = (gy == 0) ? (Hn - 1) : gy - 1;
    int yp1 = (gy == Hn - 1) ? 0 : gy + 1;
#pragma unroll
    for (int j = 0; j < 10; ++j) {
        int idx = tid + j * NTHR;
        if (idx < PATCHN) {
            int col = idx % 130;
            int t = idx / 130;
            int r = t % 3, c = t / 3;
            int gyy = (r == 0) ? ym1 : (r == 1 ? gy : yp1);
            int gx = x0 + col - 1;
            gx = (gx < 0) ? gx + Wn : (gx >= Wn ? gx - Wn : gx);
            cp4(patch_smem + idx * 4,
                x + ((size_t)(b * Cn + c) * Hn + gyy) * Wn + gx);
        }
    }
}

// ---------------------------------------------------------------------------
__global__ __launch_bounds__(NTHR, 1)
void nca_mma(const float* __restrict__ x,
             const float* __restrict__ mask,
             const float* __restrict__ b2,
             float* __restrict__ out) {
    extern __shared__ char smc[];
    float* patchf = (float*)(smc + SM_PATCH);
    float* updp   = (float*)(smc + SM_UPD);
    const uint32_t smb = smem_u32(smc);
    const uint32_t patch_smem = smb + SM_PATCH;
    const int tid  = threadIdx.x;
    const int wid  = tid >> 5;
    const int lane = tid & 31;
    const int nq   = wid & 3;          // n-quarter (24 hidden cols)
    const int mq   = wid >> 2;         // m-quarter (32 px rows)

    // ---- load all weights into SMEM once ----------------------------------
    for (int i = tid; i < 32256 / 16; i += NTHR)
        ((uint4*)(smc + SM_B1))[i] = ((const uint4*)g_B1img)[i];
    for (int i = tid; i < 4608 / 16; i += NTHR)
        ((uint4*)(smc + SM_B2))[i] = ((const uint4*)g_B2img)[i];
    __syncthreads();

    // loop-invariant fragment addresses
    const uint32_t aRow = (lane & 7) + ((lane >> 3) & 1) * 8;
    const uint32_t aK2  = ((lane >> 4) & 1) * 16;
    const uint32_t addrA0 = smb + SM_A + (mq * 32 + aRow) * ASTR + aK2;
    const uint32_t addrA1 = addrA0 + 16 * ASTR;
    const uint32_t bN  = (lane & 7) + ((lane >> 4) & 1) * 8;
    const uint32_t bK2 = ((lane >> 3) & 1) * 16;

    // ---- persistent B1 fragments: 7 k-steps x (x4: n8 grp0,1 + x2: grp2) --
    uint32_t b1f[7][6];
    {
        uint32_t a4 = smb + SM_B1 + (nq * 24 + bN) * BSTR + bK2;
        uint32_t a2 = smb + SM_B1 + (nq * 24 + 16 + (lane & 7)) * BSTR +
                      ((lane >> 3) & 1) * 16;
#pragma unroll
        for (int s = 0; s < 7; ++s) {
            ldsm4(&b1f[s][0], a4 + s * 96 * BSTR);
            ldsm2(&b1f[s][4], a2 + s * 96 * BSTR);
        }
    }
    // ---- persistent B2 fragments: this warp's two k16 tiles ---------------
    const int t0 = (3 * nq) >> 1;
    uint32_t b2f[2][4];
    ldsm4(b2f[0], smb + SM_B2 + (t0 * 16 + bN) * BSTR + bK2);
    ldsm4(b2f[1], smb + SM_B2 + ((t0 + 1) * 16 + bN) * BSTR + bK2);

    const int px128 = tid & 127;
    const int q     = tid >> 7;
    char* Ah = smc + SM_A + px128 * ASTR;
    const bool odd = nq & 1;

    int tile = blockIdx.x;
    prefetch_cp(x, tile, tid, patch_smem);
    CP_COMMIT();

    for (; tile < NT; tile += NCTA) {
        const int seg = tile % 3;
        const int t1v = tile / 3;
        const int gy  = t1v % Hn;
        const int b   = t1v / Hn;
        const int x0  = seg * PIX;

        CP_WAIT0();
        __syncthreads();                                   // sync1: patch in

        // ---- build im2col A panel (fp16), aligned ranges 32/24/32/24 ------
        if      (q == 0) buildA<0,  32>(patchf, px128, Ah);
        else if (q == 1) buildA<32, 24>(patchf, px128, Ah);
        else if (q == 2) buildA<56, 32>(patchf, px128, Ah);
        else             buildA<88, 24>(patchf, px128, Ah);
        __syncthreads();                                   // sync2: A ready

        // ---- async prefetch next tile's patch (lands during MMA) ----------
        {
            int ntile = tile + NCTA;
            if (ntile < NT) prefetch_cp(x, ntile, tid, patch_smem);
            CP_COMMIT();
        }

        // ---- stage 1: A ldsm only; B from registers -----------------------
        float d[2][3][4];
#pragma unroll
        for (int i = 0; i < 2; ++i)
#pragma unroll
            for (int f = 0; f < 3; ++f)
#pragma unroll
                for (int j = 0; j < 4; ++j) d[i][f][j] = 0.f;

#pragma unroll
        for (int s = 0; s < 7; ++s) {
            uint32_t a0[4], a1[4];
            ldsm4(a0, addrA0 + s * 32);
            ldsm4(a1, addrA1 + s * 32);
#pragma unroll
            for (int f = 0; f < 3; ++f) {
                mma16816(d[0][f], a0, b1f[s][2 * f], b1f[s][2 * f + 1]);
                mma16816(d[1][f], a1, b1f[s][2 * f], b1f[s][2 * f + 1]);
            }
        }

        // ---- stage 2: quarter k-split, k8-half zero padding ---------------
        float e[2][8];
#pragma unroll
        for (int i = 0; i < 2; ++i)
#pragma unroll
            for (int j = 0; j < 8; ++j) e[i][j] = 0.f;

#pragma unroll
        for (int mt = 0; mt < 2; ++mt) {
            uint32_t p00 = packrelu(d[mt][0][0], d[mt][0][1]);
            uint32_t p01 = packrelu(d[mt][0][2], d[mt][0][3]);
            uint32_t p10 = packrelu(d[mt][1][0], d[mt][1][1]);
            uint32_t p11 = packrelu(d[mt][1][2], d[mt][1][3]);
            uint32_t p20 = packrelu(d[mt][2][0], d[mt][2][1]);
            uint32_t p21 = packrelu(d[mt][2][2], d[mt][2][3]);
            uint32_t aA[4], aB[4];
            const uint32_t* bA;
            const uint32_t* bB;
            if (!odd) {
                aA[0] = p00; aA[1] = p01; aA[2] = p10; aA[3] = p11;
                aB[0] = p20; aB[1] = p21; aB[2] = 0;   aB[3] = 0;
                bA = b2f[0]; bB = b2f[1];
            } else {
                aA[0] = p10; aA[1] = p11; aA[2] = p20; aA[3] = p21;
                aB[0] = 0;   aB[1] = 0;   aB[2] = p00; aB[3] = p01;
                bA = b2f[1]; bB = b2f[0];
            }
            mma16816(e[mt],     aA, bA[0], bA[1]);
            mma16816(e[mt] + 4, aA, bA[2], bA[3]);
            mma16816(e[mt],     aB, bB[0], bB[1]);
            mma16816(e[mt] + 4, aB, bB[2], bB[3]);
        }

        // ---- store stage-2 partial sums (slot nq; stride 17 words) --------
        {
            int g = lane >> 2, t = lane & 3;
            float* up = updp + nq * (PIX * USTR);
#pragma unroll
            for (int mt = 0; mt < 2; ++mt) {
#pragma unroll
                for (int rr = 0; rr < 2; ++rr) {
                    int px = mq * 32 + mt * 16 + g + rr * 8;
#pragma unroll
                    for (int cc = 0; cc < 2; ++cc)
                        up[px * USTR + 2 * t + cc] = e[mt][rr * 2 + cc];
                    if (t < 2) {
#pragma unroll
                        for (int cc = 0; cc < 2; ++cc)
                            up[px * USTR + 8 + 2 * t + cc] =
                                e[mt][4 + rr * 2 + cc];
                    }
                }
            }
        }
        __syncthreads();                                   // sync3

        // ---- epilogue: out = x + (sum of 4 partials + b2) * (mask>0.5) ----
        {
            int px = tid & 127;
            float m = (mask[gy * Wn + x0 + px] > 0.5f) ? 1.f : 0.f;
#pragma unroll
            for (int k = 0; k < 3; ++k) {
                int oc = (tid >> 7) + 4 * k;
                float u = updp[px * USTR + oc] +
                          updp[PIX * USTR + px * USTR + oc] +
                          updp[2 * PIX * USTR + px * USTR + oc] +
                          updp[3 * PIX * USTR + px * USTR + oc] +
                          __ldg(b2 + oc);
                size_t off = ((size_t)(b * Cn + oc) * Hn + gy) * Wn + x0 + px;
                out[off] = fmaf(u, m, __ldg(x + off));
            }
        }
        // next iteration's sync1 guards all cross-phase hazards.
    }
}

// ---------------------------------------------------------------------------
extern "C" void kernel_launch(void* const* d_in, const int* in_sizes, int n_in,
                              void* d_out, int out_size) {
    const float* x      = (const float*)d_in[0];
    const float* w_perc = (const float*)d_in[1];
    const float* w1     = (const float*)d_in[2];
    const float* b1     = (const float*)d_in[3];
    const float* w2     = (const float*)d_in[4];
    const float* b2     = (const float*)d_in[5];
    const float* mask   = (const float*)d_in[6];
    float* out          = (float*)d_out;

    cudaFuncSetAttribute(nca_mma, cudaFuncAttributeMaxDynamicSharedMemorySize,
                         SM_TOTAL);

    fold_kernel<<<1, NTHR>>>(w1, w_perc, b1, w2);
    nca_mma<<<NCTA, NTHR, SM_TOTAL>>>(x, mask, b2, out);
}